// round 12
// baseline (speedup 1.0000x reference)
#include <cuda_runtime.h>

// Problem constants (fixed shapes from reference setup_inputs)
#define NB   2
#define C    32
#define H    64
#define W    64
#define L    (H * W)      // 4096
#define CKK  288          // C * 3 * 3
#define KHALF 144         // CKK / 2, per-warp k-range
#define O    32           // out channels
#define LOCS_PER_BLOCK 4  // 4 locations x 2 warps = 8 warps
#define THREADS 256

__device__ __forceinline__ float4 ldcs4(const float4* p) {
    return __ldcs(p);   // filters are read exactly once: evict-first
}

// TWO warps per (n, l) location (split-K): warp q handles k in
// [144q, 144q+144). Within each warp: og = lane&7 -> float4 quad of output
// channels, kg = lane>>3 -> k-slice (k = 144q + kg + 4t, 36 iters).
// Doubles warp count (16384 -> occupancy at the 64-warp/SM cap) so DRAM
// latency is hidden by thread-level parallelism, which R4-R7 showed is the
// binding resource. Partials combined via 512B smem + one barrier.
__global__ __launch_bounds__(THREADS, 8)
void convfilt_kernel(const float* __restrict__ features,
                     const float* __restrict__ filters,
                     float* __restrict__ out)
{
    __shared__ float  s_patch[LOCS_PER_BLOCK][CKK];
    __shared__ float4 s_part [LOCS_PER_BLOCK][8];   // q=1 partials, per og

    const int warp = threadIdx.x >> 5;
    const int lane = threadIdx.x & 31;
    const int slot = warp >> 1;          // location slot 0..3
    const int q    = warp & 1;           // k-half
    const int p    = blockIdx.x * LOCS_PER_BLOCK + slot;  // 0 .. N*L-1
    const int n    = p >> 12;            // / 4096
    const int l    = p & (L - 1);
    const int h    = l >> 6;
    const int w    = l & (W - 1);

    const int og = lane & 7;             // output quad: channels og*4..og*4+3
    const int kg = lane >> 3;            // k-slice within half

    const float4* __restrict__ fp = (const float4*)
        (filters + (long long)(n * L + l) * (CKK * O) + og * 4);
    const int kbase = KHALF * q;

    // ---- Phase 0: peel first two filter loads (independent of patch) ----
    const float4 f0 = ldcs4(fp + (long long)(kbase + kg    ) * 8);   // t=0
    const float4 f1 = ldcs4(fp + (long long)(kbase + kg + 4) * 8);   // t=1

    // ---- Phase 1: warp pair co-builds the unfold patch (64 threads) ----
    for (int k = lane + 32 * q; k < CKK; k += 64) {
        const int c  = k / 9;
        const int r  = k - c * 9;
        const int kh = r / 3;
        const int kw = r - kh * 3;
        const int hh = h + kh - 1;
        const int ww = w + kw - 1;
        float v = 0.0f;
        if ((unsigned)hh < (unsigned)H && (unsigned)ww < (unsigned)W)
            v = features[((n * C + c) * H + hh) * W + ww];
        s_patch[slot][k] = v;
    }
    __syncthreads();

    // ---- Phase 2: consume peeled loads, then stream this half ----
    float4 acc = make_float4(0.f, 0.f, 0.f, 0.f);
    {
        const float s0 = s_patch[slot][kbase + kg];
        acc.x = fmaf(s0, f0.x, acc.x);
        acc.y = fmaf(s0, f0.y, acc.y);
        acc.z = fmaf(s0, f0.z, acc.z);
        acc.w = fmaf(s0, f0.w, acc.w);
        const float s1 = s_patch[slot][kbase + kg + 4];
        acc.x = fmaf(s1, f1.x, acc.x);
        acc.y = fmaf(s1, f1.y, acc.y);
        acc.z = fmaf(s1, f1.z, acc.z);
        acc.w = fmaf(s1, f1.w, acc.w);
    }

    #pragma unroll 9
    for (int t = 2; t < KHALF / 4; ++t) {          // 34 more iterations
        const int k = kbase + kg + 4 * t;
        const float s  = s_patch[slot][k];
        const float4 f = ldcs4(fp + (long long)k * 8);
        acc.x = fmaf(s, f.x, acc.x);
        acc.y = fmaf(s, f.y, acc.y);
        acc.z = fmaf(s, f.z, acc.z);
        acc.w = fmaf(s, f.w, acc.w);
    }

    // ---- Reduce across the 4 k-slices within the warp ----
    #pragma unroll
    for (int m = 8; m <= 16; m <<= 1) {
        acc.x += __shfl_xor_sync(0xffffffffu, acc.x, m);
        acc.y += __shfl_xor_sync(0xffffffffu, acc.y, m);
        acc.z += __shfl_xor_sync(0xffffffffu, acc.z, m);
        acc.w += __shfl_xor_sync(0xffffffffu, acc.w, m);
    }

    // ---- Combine the two k-halves through shared memory ----
    if (q == 1 && kg == 0)
        s_part[slot][og] = acc;
    __syncthreads();

    if (q == 0 && kg == 0) {
        const float4 b = s_part[slot][og];
        const int obase = og * 4;
        __stcs(&out[(n * O + obase + 0) * L + l], fmaxf(acc.x + b.x, 0.0f));
        __stcs(&out[(n * O + obase + 1) * L + l], fmaxf(acc.y + b.y, 0.0f));
        __stcs(&out[(n * O + obase + 2) * L + l], fmaxf(acc.z + b.z, 0.0f));
        __stcs(&out[(n * O + obase + 3) * L + l], fmaxf(acc.w + b.w, 0.0f));
    }
}

extern "C" void kernel_launch(void* const* d_in, const int* in_sizes, int n_in,
                              void* d_out, int out_size)
{
    const float* features = (const float*)d_in[0];  // [2,32,64,64]
    const float* filters  = (const float*)d_in[1];  // [2,4096,288,32]
    float* out = (float*)d_out;                     // [2,32,64,64]

    const int grid = (NB * L) / LOCS_PER_BLOCK;     // 2048 blocks
    convfilt_kernel<<<grid, THREADS>>>(features, filters, out);
}

// round 13
// speedup vs baseline: 1.0326x; 1.0326x over previous
#include <cuda_runtime.h>
#include <cuda_pipeline.h>

// Problem constants (fixed shapes from reference setup_inputs)
#define NB   2
#define C    32
#define H    64
#define W    64
#define L    (H * W)      // 4096
#define CKK  288          // C * 3 * 3
#define O    32           // out channels
#define WARPS_PER_BLOCK 8
#define THREADS (WARPS_PER_BLOCK * 32)
#define NSTAGE 4          // cp.async pipeline depth (per-warp smem ring)
#define NT     (CKK / 4)  // 72 pipeline steps

// One warp per (n, l) location. Filter loads go through cp.async (LDGSTS)
// into a 4-stage smem ring: in-flight bytes cost SMEM, not registers, which
// breaks the register-scoreboard MLP cap that pinned every LDG variant at
// ~6.1 TB/s. Each lane consumes only the 16B it issued itself -> no syncs.
// lane split: og = lane&7 -> float4 quad of output channels,
//             kg = lane>>3 -> k-slice (k = kg + 4t).
__global__ __launch_bounds__(THREADS, 8)
void convfilt_kernel(const float* __restrict__ features,
                     const float* __restrict__ filters,
                     float* __restrict__ out)
{
    __shared__ float  s_patch[WARPS_PER_BLOCK][CKK];
    __shared__ float4 s_ring [WARPS_PER_BLOCK][NSTAGE][32];

    const int warp = threadIdx.x >> 5;
    const int lane = threadIdx.x & 31;
    const int gw   = blockIdx.x * WARPS_PER_BLOCK + warp;  // 0 .. N*L-1
    const int n    = gw >> 12;        // / 4096
    const int l    = gw & (L - 1);
    const int h    = l >> 6;
    const int w    = l & (W - 1);

    const int og = lane & 7;    // output quad: channels og*4 .. og*4+3
    const int kg = lane >> 3;   // k-slice: k = kg, kg+4, ...

    const float4* __restrict__ fp = (const float4*)
        (filters + (long long)(n * L + l) * (CKK * O) + og * 4);
    // element k, quad og lives at fp[k * 8]

    // ---- Prologue: fill the pipeline (4 stages x 512B/warp in flight) ----
    #pragma unroll
    for (int d = 0; d < NSTAGE; ++d) {
        const int k = kg + 4 * d;
        __pipeline_memcpy_async(&s_ring[warp][d][lane],
                                fp + (long long)k * 8, sizeof(float4));
        __pipeline_commit();
    }

    // ---- Build unfold patch while cp.asyncs are in flight ----
    #pragma unroll
    for (int k = lane; k < CKK; k += 32) {
        const int c  = k / 9;
        const int r  = k - c * 9;
        const int kh = r / 3;
        const int kw = r - kh * 3;
        const int hh = h + kh - 1;
        const int ww = w + kw - 1;
        float v = 0.0f;
        if ((unsigned)hh < (unsigned)H && (unsigned)ww < (unsigned)W)
            v = features[((n * C + c) * H + hh) * W + ww];
        s_patch[warp][k] = v;
    }
    __syncwarp();

    // ---- Main pipeline: consume stage t, issue stage t+NSTAGE ----
    float4 acc = make_float4(0.f, 0.f, 0.f, 0.f);
    #pragma unroll 8
    for (int t = 0; t < NT; ++t) {
        __pipeline_wait_prior(NSTAGE - 1);        // stage t complete
        const float4 f = s_ring[warp][t & (NSTAGE - 1)][lane];
        const float  s = s_patch[warp][kg + 4 * t];

        const int tn = t + NSTAGE;
        if (tn < NT) {
            const int k = kg + 4 * tn;
            __pipeline_memcpy_async(&s_ring[warp][t & (NSTAGE - 1)][lane],
                                    fp + (long long)k * 8, sizeof(float4));
        }
        __pipeline_commit();                      // keep group count aligned

        acc.x = fmaf(s, f.x, acc.x);
        acc.y = fmaf(s, f.y, acc.y);
        acc.z = fmaf(s, f.z, acc.z);
        acc.w = fmaf(s, f.w, acc.w);
    }

    // ---- Reduce across the 4 k-slices (lanes differing in bits 3,4) ----
    #pragma unroll
    for (int m = 8; m <= 16; m <<= 1) {
        acc.x += __shfl_xor_sync(0xffffffffu, acc.x, m);
        acc.y += __shfl_xor_sync(0xffffffffu, acc.y, m);
        acc.z += __shfl_xor_sync(0xffffffffu, acc.z, m);
        acc.w += __shfl_xor_sync(0xffffffffu, acc.w, m);
    }

    // lanes 0..7 (kg==0) hold the full sums for channels og*4 .. og*4+3
    if (kg == 0) {
        const int obase = og * 4;
        __stcs(&out[(n * O + obase + 0) * L + l], fmaxf(acc.x, 0.0f));
        __stcs(&out[(n * O + obase + 1) * L + l], fmaxf(acc.y, 0.0f));
        __stcs(&out[(n * O + obase + 2) * L + l], fmaxf(acc.z, 0.0f));
        __stcs(&out[(n * O + obase + 3) * L + l], fmaxf(acc.w, 0.0f));
    }
}

extern "C" void kernel_launch(void* const* d_in, const int* in_sizes, int n_in,
                              void* d_out, int out_size)
{
    const float* features = (const float*)d_in[0];  // [2,32,64,64]
    const float* filters  = (const float*)d_in[1];  // [2,4096,288,32]
    float* out = (float*)d_out;                     // [2,32,64,64]

    const int total_warps = NB * L;                 // 8192
    const int grid = total_warps / WARPS_PER_BLOCK; // 1024
    convfilt_kernel<<<grid, THREADS>>>(features, filters, out);
}

// round 14
// speedup vs baseline: 1.0792x; 1.0452x over previous
#include <cuda_runtime.h>

// Problem constants (fixed shapes from reference setup_inputs)
#define NB   2
#define C    32
#define H    64
#define W    64
#define L    (H * W)      // 4096
#define CKK  288          // C * 3 * 3
#define O    32           // out channels
#define WARPS_PER_BLOCK 8
#define THREADS (WARPS_PER_BLOCK * 32)

__device__ __forceinline__ float4 ldcs4(const float4* p) {
    return __ldcs(p);   // filters are read exactly once: evict-first
}

// R5 configuration (fastest measured kernel: 49.9us, 6164 GB/s) + staged
// coalesced output. One warp per (n,l); block = 8 consecutive locations.
// Phase 0: peel 2 filter loads. Phase 1: build unfold patch. Phase 2: rolled
// unroll-7 LDG.128 stream, 4 FMA chains, shfl reduction. Epilogue: stage the
// 8x32 results in smem and write them sector-coalesced (8 consecutive l per
// 8-thread group) instead of 32 scattered 4B stores per warp.
__global__ __launch_bounds__(THREADS, 8)
void convfilt_kernel(const float* __restrict__ features,
                     const float* __restrict__ filters,
                     float* __restrict__ out)
{
    __shared__ float s_patch[WARPS_PER_BLOCK][CKK];
    __shared__ float s_out[WARPS_PER_BLOCK][O + 1];   // +1: bank-conflict pad

    const int warp = threadIdx.x >> 5;
    const int lane = threadIdx.x & 31;
    const int gw   = blockIdx.x * WARPS_PER_BLOCK + warp;  // 0 .. N*L-1
    const int n    = gw >> 12;        // / 4096
    const int l    = gw & (L - 1);
    const int h    = l >> 6;
    const int w    = l & (W - 1);

    const int og = lane & 7;    // output quad: channels og*4 .. og*4+3
    const int kg = lane >> 3;   // k-slice: k = kg, kg+4, kg+8, ...

    const float4* __restrict__ fp = (const float4*)
        (filters + (long long)(n * L + l) * (CKK * O) + og * 4);
    // element k, quad og lives at fp[k * (O/4)] = fp[k * 8]

    // ---- Phase 0: peel first two filter loads (independent of patch) ----
    const float4 f0 = ldcs4(fp + (long long)(kg    ) * 8);   // t = 0
    const float4 f1 = ldcs4(fp + (long long)(kg + 4) * 8);   // t = 1

    // ---- Phase 1: build unfold patch (k = c*9 + kh*3 + kw) ----
    #pragma unroll
    for (int k = lane; k < CKK; k += 32) {
        const int c  = k / 9;
        const int r  = k - c * 9;
        const int kh = r / 3;
        const int kw = r - kh * 3;
        const int hh = h + kh - 1;
        const int ww = w + kw - 1;
        float v = 0.0f;
        if ((unsigned)hh < (unsigned)H && (unsigned)ww < (unsigned)W)
            v = features[((n * C + c) * H + hh) * W + ww];
        s_patch[warp][k] = v;
    }
    __syncwarp();

    // ---- Phase 2: consume peeled loads, then stream the rest ----
    float4 acc = make_float4(0.f, 0.f, 0.f, 0.f);
    {
        const float s0 = s_patch[warp][kg];
        acc.x = fmaf(s0, f0.x, acc.x);
        acc.y = fmaf(s0, f0.y, acc.y);
        acc.z = fmaf(s0, f0.z, acc.z);
        acc.w = fmaf(s0, f0.w, acc.w);
        const float s1 = s_patch[warp][kg + 4];
        acc.x = fmaf(s1, f1.x, acc.x);
        acc.y = fmaf(s1, f1.y, acc.y);
        acc.z = fmaf(s1, f1.z, acc.z);
        acc.w = fmaf(s1, f1.w, acc.w);
    }

    #pragma unroll 7
    for (int t = 2; t < CKK / 4; ++t) {          // 70 iterations
        const int k = kg + 4 * t;
        const float s  = s_patch[warp][k];
        const float4 f = ldcs4(fp + (long long)k * 8);
        acc.x = fmaf(s, f.x, acc.x);
        acc.y = fmaf(s, f.y, acc.y);
        acc.z = fmaf(s, f.z, acc.z);
        acc.w = fmaf(s, f.w, acc.w);
    }

    // ---- Reduce across the 4 k-slices (lanes differing in bits 3,4) ----
    #pragma unroll
    for (int m = 8; m <= 16; m <<= 1) {
        acc.x += __shfl_xor_sync(0xffffffffu, acc.x, m);
        acc.y += __shfl_xor_sync(0xffffffffu, acc.y, m);
        acc.z += __shfl_xor_sync(0xffffffffu, acc.z, m);
        acc.w += __shfl_xor_sync(0xffffffffu, acc.w, m);
    }

    // ---- Stage results: lanes 0..7 hold sums for channels og*4..og*4+3 ----
    if (kg == 0) {
        const int obase = og * 4;
        s_out[warp][obase + 0] = fmaxf(acc.x, 0.0f);
        s_out[warp][obase + 1] = fmaxf(acc.y, 0.0f);
        s_out[warp][obase + 2] = fmaxf(acc.z, 0.0f);
        s_out[warp][obase + 3] = fmaxf(acc.w, 0.0f);
    }
    __syncthreads();

    // ---- Coalesced epilogue: 256 threads write 8 locations x 32 channels.
    // thread t -> channel o = t>>3, location offset lo = t&7: each 8-thread
    // group writes 8 consecutive floats (one aligned 32B sector) of row
    // (n, o). blockIdx*8 is 8-aligned within L, so sectors are aligned.
    {
        const int o  = threadIdx.x >> 3;
        const int lo = threadIdx.x & 7;
        const int lbase = (blockIdx.x * WARPS_PER_BLOCK) & (L - 1);
        __stcs(&out[(n * O + o) * L + lbase + lo], s_out[lo][o]);
    }
}

extern "C" void kernel_launch(void* const* d_in, const int* in_sizes, int n_in,
                              void* d_out, int out_size)
{
    const float* features = (const float*)d_in[0];  // [2,32,64,64]
    const float* filters  = (const float*)d_in[1];  // [2,4096,288,32]
    float* out = (float*)d_out;                     // [2,32,64,64]

    const int total_warps = NB * L;                 // 8192
    const int grid = total_warps / WARPS_PER_BLOCK; // 1024
    convfilt_kernel<<<grid, THREADS>>>(features, filters, out);
}

// round 15
// speedup vs baseline: 1.0799x; 1.0006x over previous
#include <cuda_runtime.h>

// Problem constants (fixed shapes from reference setup_inputs)
#define NB   2
#define C    32
#define H    64
#define W    64
#define L    (H * W)      // 4096
#define CKK  288          // C * 3 * 3
#define O    32           // out channels
#define WARPS_PER_BLOCK 8
#define THREADS (WARPS_PER_BLOCK * 32)

__device__ __forceinline__ float4 ldcs4(const float4* p) {
    return __ldcs(p);   // filters are read exactly once: evict-first
}

// Roofline-converged config (49.95us kernel, 6.14 TB/s = measured chip
// ceiling; traffic == logical minimum 306MB). One warp per (n,l); block = 8
// consecutive locations, single wave (1024 blocks, 8/SM resident).
// Phase 0: peel 3 filter loads (prologue DRAM in flight during patch build).
// Phase 1: build unfold patch from L2-resident features.
// Phase 2: rolled LDG.128 stream, 4 FMA chains, shfl_xor(8,16) reduction.
// Epilogue: stage 8x32 results transposed in smem; 64 threads emit STG.128
// full-sector stores.
__global__ __launch_bounds__(THREADS, 8)
void convfilt_kernel(const float* __restrict__ features,
                     const float* __restrict__ filters,
                     float* __restrict__ out)
{
    __shared__ float s_patch[WARPS_PER_BLOCK][CKK];
    __shared__ float s_out[O][WARPS_PER_BLOCK];   // [channel][location]

    const int warp = threadIdx.x >> 5;
    const int lane = threadIdx.x & 31;
    const int gw   = blockIdx.x * WARPS_PER_BLOCK + warp;  // 0 .. N*L-1
    const int n    = gw >> 12;        // / 4096
    const int l    = gw & (L - 1);
    const int h    = l >> 6;
    const int w    = l & (W - 1);

    const int og = lane & 7;    // output quad: channels og*4 .. og*4+3
    const int kg = lane >> 3;   // k-slice: k = kg, kg+4, kg+8, ...

    const float4* __restrict__ fp = (const float4*)
        (filters + (long long)(n * L + l) * (CKK * O) + og * 4);
    // element k, quad og lives at fp[k * (O/4)] = fp[k * 8]

    // ---- Phase 0: peel first three filter loads (independent of patch) ----
    const float4 f0 = ldcs4(fp + (long long)(kg    ) * 8);   // t = 0
    const float4 f1 = ldcs4(fp + (long long)(kg + 4) * 8);   // t = 1
    const float4 f2 = ldcs4(fp + (long long)(kg + 8) * 8);   // t = 2

    // ---- Phase 1: build unfold patch (k = c*9 + kh*3 + kw) ----
    #pragma unroll
    for (int k = lane; k < CKK; k += 32) {
        const int c  = k / 9;
        const int r  = k - c * 9;
        const int kh = r / 3;
        const int kw = r - kh * 3;
        const int hh = h + kh - 1;
        const int ww = w + kw - 1;
        float v = 0.0f;
        if ((unsigned)hh < (unsigned)H && (unsigned)ww < (unsigned)W)
            v = features[((n * C + c) * H + hh) * W + ww];
        s_patch[warp][k] = v;
    }
    __syncwarp();

    // ---- Phase 2: consume peeled loads, then stream the rest ----
    float4 acc = make_float4(0.f, 0.f, 0.f, 0.f);
    {
        const float s0 = s_patch[warp][kg];
        acc.x = fmaf(s0, f0.x, acc.x);
        acc.y = fmaf(s0, f0.y, acc.y);
        acc.z = fmaf(s0, f0.z, acc.z);
        acc.w = fmaf(s0, f0.w, acc.w);
        const float s1 = s_patch[warp][kg + 4];
        acc.x = fmaf(s1, f1.x, acc.x);
        acc.y = fmaf(s1, f1.y, acc.y);
        acc.z = fmaf(s1, f1.z, acc.z);
        acc.w = fmaf(s1, f1.w, acc.w);
        const float s2 = s_patch[warp][kg + 8];
        acc.x = fmaf(s2, f2.x, acc.x);
        acc.y = fmaf(s2, f2.y, acc.y);
        acc.z = fmaf(s2, f2.z, acc.z);
        acc.w = fmaf(s2, f2.w, acc.w);
    }

    #pragma unroll 7
    for (int t = 3; t < CKK / 4; ++t) {          // 69 iterations
        const int k = kg + 4 * t;
        const float s  = s_patch[warp][k];
        const float4 f = ldcs4(fp + (long long)k * 8);
        acc.x = fmaf(s, f.x, acc.x);
        acc.y = fmaf(s, f.y, acc.y);
        acc.z = fmaf(s, f.z, acc.z);
        acc.w = fmaf(s, f.w, acc.w);
    }

    // ---- Reduce across the 4 k-slices (lanes differing in bits 3,4) ----
    #pragma unroll
    for (int m = 8; m <= 16; m <<= 1) {
        acc.x += __shfl_xor_sync(0xffffffffu, acc.x, m);
        acc.y += __shfl_xor_sync(0xffffffffu, acc.y, m);
        acc.z += __shfl_xor_sync(0xffffffffu, acc.z, m);
        acc.w += __shfl_xor_sync(0xffffffffu, acc.w, m);
    }

    // ---- Stage results transposed: s_out[channel][location] ----
    if (kg == 0) {
        const int obase = og * 4;
        s_out[obase + 0][warp] = fmaxf(acc.x, 0.0f);
        s_out[obase + 1][warp] = fmaxf(acc.y, 0.0f);
        s_out[obase + 2][warp] = fmaxf(acc.z, 0.0f);
        s_out[obase + 3][warp] = fmaxf(acc.w, 0.0f);
    }
    __syncthreads();

    // ---- Epilogue: 64 threads write 8 locations x 32 channels as STG.128.
    // thread t -> channel o = t>>1, location quad lo4 = (t&1)*4: one float4
    // (16B) per thread, pairs of threads cover the 32B span of row (n,o).
    // blockIdx*8 is 8-aligned within L -> 16B-aligned addresses.
    if (threadIdx.x < 64) {
        const int o   = threadIdx.x >> 1;
        const int lo4 = (threadIdx.x & 1) * 4;
        const int lbase = (blockIdx.x * WARPS_PER_BLOCK) & (L - 1);
        const float4 v = *(const float4*)&s_out[o][lo4];
        __stcs((float4*)&out[(n * O + o) * L + lbase + lo4], v);
    }
}

extern "C" void kernel_launch(void* const* d_in, const int* in_sizes, int n_in,
                              void* d_out, int out_size)
{
    const float* features = (const float*)d_in[0];  // [2,32,64,64]
    const float* filters  = (const float*)d_in[1];  // [2,4096,288,32]
    float* out = (float*)d_out;                     // [2,32,64,64]

    const int total_warps = NB * L;                 // 8192
    const int grid = total_warps / WARPS_PER_BLOCK; // 1024
    convfilt_kernel<<<grid, THREADS>>>(features, filters, out);
}